// round 6
// baseline (speedup 1.0000x reference)
#include <cuda_runtime.h>
#include <cuda_bf16.h>
#include <math.h>

// Problem constants (shapes fixed by the dataset)
#define MAXM 50000
#define MAXE 600000
#define MAXN 100000
// D = 128 floats = 32 float4 per row

// ---------------- device scratch (static: no allocations allowed) -----------
__device__ float  g_deg[MAXM];
__device__ float  g_dis[MAXM];
__device__ int    g_cnt[MAXM];
__device__ int    g_rowptr[MAXM + 1];
__device__ int    g_cursor[MAXM];
__device__ float2 g_cw[MAXE];        // packed (col as bits, normalized weight)
__device__ float4 g_s0[MAXM * 32];   // 25.6 MB
__device__ float4 g_s1[MAXM * 32];   // 25.6 MB
__device__ int    g_srcmap[MAXN];

// ---------------- preprocessing kernels ------------------------------------
__global__ void k_init(int M, int N) {
    int i = blockIdx.x * blockDim.x + threadIdx.x;
    if (i < M) { g_deg[i] = 0.f; g_cnt[i] = 0; }
    if (i < N) g_srcmap[i] = -1;
}

__global__ void k_degcnt(const int* __restrict__ row,
                         const float* __restrict__ val, int E) {
    int e = blockIdx.x * blockDim.x + threadIdx.x;
    if (e < E) {
        int r = row[e];
        atomicAdd(&g_deg[r], val[e]);
        atomicAdd(&g_cnt[r], 1);
    }
}

__global__ void k_dis(int M) {
    int i = blockIdx.x * blockDim.x + threadIdx.x;
    if (i < M) g_dis[i] = rsqrtf(g_deg[i] + 1e-8f);
}

// single-block exclusive scan of g_cnt -> g_rowptr / g_cursor
__global__ void k_scan(int M, int E) {
    __shared__ int sums[1024];
    int t = threadIdx.x;
    int CH = (M + 1023) >> 10;
    int b = t * CH;
    int s = 0;
    for (int i = 0; i < CH; i++) {
        int idx = b + i;
        if (idx < M) s += g_cnt[idx];
    }
    sums[t] = s;
    __syncthreads();
    for (int off = 1; off < 1024; off <<= 1) {
        int v = (t >= off) ? sums[t - off] : 0;
        __syncthreads();
        sums[t] += v;
        __syncthreads();
    }
    int excl = (t == 0) ? 0 : sums[t - 1];
    for (int i = 0; i < CH; i++) {
        int idx = b + i;
        if (idx < M) {
            g_rowptr[idx] = excl;
            g_cursor[idx] = excl;
            excl += g_cnt[idx];
        }
    }
    if (t == 0) g_rowptr[M] = E;
}

// scatter edges into CSR slots, fusing the symmetric-normalization multiply
__global__ void k_scatter(const int* __restrict__ row, const int* __restrict__ col,
                          const float* __restrict__ val, int E) {
    int e = blockIdx.x * blockDim.x + threadIdx.x;
    if (e < E) {
        int r = row[e];
        int c = col[e];
        float nv = val[e] * g_dis[r] * g_dis[c];
        int p = atomicAdd(&g_cursor[r], 1);
        g_cw[p] = make_float2(__int_as_float(c), nv);
    }
}

// subset gather: s0[m] = features[index[m]]; srcmap[index[m]] = m
__global__ void k_gather0(const float* __restrict__ features,
                          const int* __restrict__ index, int M) {
    int i = blockIdx.x * blockDim.x + threadIdx.x;
    if (i < M * 32) {
        int m = i >> 5;
        int q = i & 31;
        int src = index[m];
        if (q == 0) g_srcmap[src] = m;
        g_s0[m * 32 + q] = ((const float4*)features)[(size_t)src * 32 + q];
    }
}

// ---------------- SpMM: warp per row, 4 gathers in flight -------------------
__global__ void __launch_bounds__(256) k_spmm(int srcsel, int M) {
    const float4* __restrict__ src = srcsel ? (const float4*)g_s1 : (const float4*)g_s0;
    float4* __restrict__ dst       = srcsel ? (float4*)g_s0       : (float4*)g_s1;
    int gw   = (blockIdx.x * blockDim.x + threadIdx.x) >> 5;
    int lane = threadIdx.x & 31;
    if (gw >= M) return;
    int e   = g_rowptr[gw];
    int end = g_rowptr[gw + 1];
    float4 acc = make_float4(0.f, 0.f, 0.f, 0.f);

    int n4 = e + ((end - e) & ~3);
    for (; e < n4; e += 4) {
        float2 p0 = __ldg(g_cw + e);
        float2 p1 = __ldg(g_cw + e + 1);
        float2 p2 = __ldg(g_cw + e + 2);
        float2 p3 = __ldg(g_cw + e + 3);
        int c0 = __float_as_int(p0.x);
        int c1 = __float_as_int(p1.x);
        int c2 = __float_as_int(p2.x);
        int c3 = __float_as_int(p3.x);
        float4 v0 = __ldg(src + c0 * 32 + lane);
        float4 v1 = __ldg(src + c1 * 32 + lane);
        float4 v2 = __ldg(src + c2 * 32 + lane);
        float4 v3 = __ldg(src + c3 * 32 + lane);
        acc.x = fmaf(p0.y, v0.x, acc.x); acc.y = fmaf(p0.y, v0.y, acc.y);
        acc.z = fmaf(p0.y, v0.z, acc.z); acc.w = fmaf(p0.y, v0.w, acc.w);
        acc.x = fmaf(p1.y, v1.x, acc.x); acc.y = fmaf(p1.y, v1.y, acc.y);
        acc.z = fmaf(p1.y, v1.z, acc.z); acc.w = fmaf(p1.y, v1.w, acc.w);
        acc.x = fmaf(p2.y, v2.x, acc.x); acc.y = fmaf(p2.y, v2.y, acc.y);
        acc.z = fmaf(p2.y, v2.z, acc.z); acc.w = fmaf(p2.y, v2.w, acc.w);
        acc.x = fmaf(p3.y, v3.x, acc.x); acc.y = fmaf(p3.y, v3.y, acc.y);
        acc.z = fmaf(p3.y, v3.z, acc.z); acc.w = fmaf(p3.y, v3.w, acc.w);
    }
    for (; e < end; e++) {
        float2 p0 = __ldg(g_cw + e);
        int c0 = __float_as_int(p0.x);
        float4 v0 = __ldg(src + c0 * 32 + lane);
        acc.x = fmaf(p0.y, v0.x, acc.x); acc.y = fmaf(p0.y, v0.y, acc.y);
        acc.z = fmaf(p0.y, v0.z, acc.z); acc.w = fmaf(p0.y, v0.w, acc.w);
    }
    dst[gw * 32 + lane] = acc;
}

// ---------------- fused MLP head --------------------------------------------
// 64 nodes per block, 256 threads. x staged in smem [64][132], weights from L1.
__device__ __forceinline__ float leaky(float v) { return v > 0.f ? v : 0.01f * v; }

__global__ void __launch_bounds__(256) k_mlp(
    const float* __restrict__ feat,
    const float* __restrict__ W1, const float* __restrict__ b1,
    const float* __restrict__ W2, const float* __restrict__ b2,
    const float* __restrict__ W3, const float* __restrict__ b3,
    const float* __restrict__ W4,
    float* __restrict__ out, int Ntot)
{
    __shared__ float xs[64 * 132];            // 33.8 KB, reused for h1/h2/h3
    float* h1s = xs;                          // [64][68]  (after sync)
    float* h2s = xs + 64 * 68;                // [64][36]
    float* h3s = xs + 64 * 68 + 64 * 36;      // [64][24]

    int t  = threadIdx.x;
    int nb = blockIdx.x * 64;

    // ---- stage x: final features row per node (s1 for propagated nodes) ----
    for (int i = t; i < 64 * 32; i += 256) {
        int n  = i >> 5;
        int c4 = i & 31;
        int gn = nb + n;
        float4 v = make_float4(0.f, 0.f, 0.f, 0.f);
        if (gn < Ntot) {
            int sm_ = g_srcmap[gn];
            const float4* src = (sm_ >= 0) ? ((const float4*)g_s1) + (size_t)sm_ * 32
                                           : ((const float4*)feat) + (size_t)gn * 32;
            v = __ldg(src + c4);
        }
        *(float4*)&xs[n * 132 + c4 * 4] = v;
    }
    __syncthreads();

    int nq = t >> 5, jl = t & 31, n0 = nq * 8;

    // ---- GEMM1: [64x128] @ W1[128x64] + b1, leaky ----
    float a0[8], a1[8];
#pragma unroll
    for (int i = 0; i < 8; i++) { a0[i] = 0.f; a1[i] = 0.f; }
#pragma unroll 4
    for (int k = 0; k < 128; k++) {
        float w0 = __ldg(W1 + k * 64 + jl);
        float w1 = __ldg(W1 + k * 64 + jl + 32);
#pragma unroll
        for (int i = 0; i < 8; i++) {
            float xv = xs[(n0 + i) * 132 + k];
            a0[i] = fmaf(xv, w0, a0[i]);
            a1[i] = fmaf(xv, w1, a1[i]);
        }
    }
    __syncthreads();   // done reading xs; h1s aliases it
    {
        float bb0 = __ldg(b1 + jl), bb1 = __ldg(b1 + jl + 32);
#pragma unroll
        for (int i = 0; i < 8; i++) {
            h1s[(n0 + i) * 68 + jl]      = leaky(a0[i] + bb0);
            h1s[(n0 + i) * 68 + jl + 32] = leaky(a1[i] + bb1);
        }
    }
    __syncthreads();

    // ---- GEMM2: [64x64] @ W2[64x32] + b2, leaky ----
    float a2[8];
#pragma unroll
    for (int i = 0; i < 8; i++) a2[i] = 0.f;
#pragma unroll 4
    for (int k = 0; k < 64; k++) {
        float w = __ldg(W2 + k * 32 + jl);
#pragma unroll
        for (int i = 0; i < 8; i++)
            a2[i] = fmaf(h1s[(n0 + i) * 68 + k], w, a2[i]);
    }
    __syncthreads();
    {
        float bb = __ldg(b2 + jl);
#pragma unroll
        for (int i = 0; i < 8; i++)
            h2s[(n0 + i) * 36 + jl] = leaky(a2[i] + bb);
    }
    __syncthreads();

    // ---- GEMM3: [64x32] @ W3[32x21] + b3, leaky ----
    float a3[8];
#pragma unroll
    for (int i = 0; i < 8; i++) a3[i] = 0.f;
    if (jl < 21) {
#pragma unroll 4
        for (int k = 0; k < 32; k++) {
            float w = __ldg(W3 + k * 21 + jl);
#pragma unroll
            for (int i = 0; i < 8; i++)
                a3[i] = fmaf(h2s[(n0 + i) * 36 + k], w, a3[i]);
        }
    }
    __syncthreads();
    if (jl < 21) {
        float bb = __ldg(b3 + jl);
#pragma unroll
        for (int i = 0; i < 8; i++)
            h3s[(n0 + i) * 24 + jl] = leaky(a3[i] + bb);
    }
    __syncthreads();

    // ---- GEMM4 + sigmoid: [64x21] @ W4[21x1] ----
    if (t < 64) {
        int gn = nb + t;
        if (gn < Ntot) {
            float s = 0.f;
#pragma unroll
            for (int k = 0; k < 21; k++)
                s = fmaf(h3s[t * 24 + k], __ldg(W4 + k), s);
            out[gn] = 1.f / (1.f + expf(-s));
        }
    }
}

// ---------------- launch -----------------------------------------------------
extern "C" void kernel_launch(void* const* d_in, const int* in_sizes, int n_in,
                              void* d_out, int out_size) {
    const float* features = (const float*)d_in[0];
    const int*   index    = (const int*)d_in[1];
    const int*   erow     = (const int*)d_in[2];
    const int*   ecol     = (const int*)d_in[3];
    const float* eval_    = (const float*)d_in[4];
    const float* W1 = (const float*)d_in[5];
    const float* b1 = (const float*)d_in[6];
    const float* W2 = (const float*)d_in[7];
    const float* b2 = (const float*)d_in[8];
    const float* W3 = (const float*)d_in[9];
    const float* b3 = (const float*)d_in[10];
    const float* W4 = (const float*)d_in[11];

    int M = in_sizes[1];
    int E = in_sizes[2];
    int N = out_size;            // [N, 1] fp32 output
    float* out = (float*)d_out;

    const int TB = 256;
    k_init   <<<(N + TB - 1) / TB, TB>>>(M, N);
    k_degcnt <<<(E + TB - 1) / TB, TB>>>(erow, eval_, E);
    k_dis    <<<(M + TB - 1) / TB, TB>>>(M);
    k_scan   <<<1, 1024>>>(M, E);
    k_scatter<<<(E + TB - 1) / TB, TB>>>(erow, ecol, eval_, E);
    k_gather0<<<(M * 32 + TB - 1) / TB, TB>>>(features, index, M);

    int spmmBlocks = (M * 32 + TB - 1) / TB;
    k_spmm<<<spmmBlocks, TB>>>(0, M);   // s0 -> s1
    k_spmm<<<spmmBlocks, TB>>>(1, M);   // s1 -> s0
    k_spmm<<<spmmBlocks, TB>>>(0, M);   // s0 -> s1  (final in s1)

    k_mlp<<<(N + 63) / 64, 256>>>(features, W1, b1, W2, b2, W3, b3, W4, out, N);
}

// round 8
// speedup vs baseline: 1.3579x; 1.3579x over previous
#include <cuda_runtime.h>
#include <cuda_bf16.h>
#include <math.h>

// Problem constants (shapes fixed by the dataset)
#define MAXM 50000
#define MAXE 600000
#define MAXN 100000
// D = 128 floats = 32 float4 per row

// ---------------- device scratch (static: no allocations allowed) -----------
__device__ float  g_deg[MAXM];
__device__ float  g_dis[MAXM];
__device__ int    g_cnt[MAXM];
__device__ int    g_rowptr[MAXM + 1];
__device__ int    g_cursor[MAXM];
__device__ int    g_bsum[64];
__device__ float2 g_cw[MAXE];        // packed (col as bits, normalized weight)
__device__ float4 g_s0[MAXM * 32];   // 25.6 MB
__device__ float4 g_s1[MAXM * 32];   // 25.6 MB
__device__ int    g_srcmap[MAXN];

// ---------------- preprocessing kernels ------------------------------------
__global__ void k_init(int M, int N) {
    int i = blockIdx.x * blockDim.x + threadIdx.x;
    if (i < M) { g_deg[i] = 0.f; g_cnt[i] = 0; }
    if (i < N) g_srcmap[i] = -1;
}

__global__ void k_degcnt(const int* __restrict__ row,
                         const float* __restrict__ val, int E) {
    int e = blockIdx.x * blockDim.x + threadIdx.x;
    if (e < E) {
        int r = row[e];
        atomicAdd(&g_deg[r], val[e]);
        atomicAdd(&g_cnt[r], 1);
    }
}

__global__ void k_dis(int M) {
    int i = blockIdx.x * blockDim.x + threadIdx.x;
    if (i < M) g_dis[i] = rsqrtf(g_deg[i] + 1e-8f);
}

// ---- 3-phase device-wide exclusive scan of g_cnt -> g_rowptr/g_cursor ------
// Phase 1: per-block (1024-wide) local exclusive scan; block totals to g_bsum.
__global__ void __launch_bounds__(1024) k_scan1(int M) {
    __shared__ int sh[1024];
    int t = threadIdx.x;
    int i = blockIdx.x * 1024 + t;
    int v = (i < M) ? g_cnt[i] : 0;
    sh[t] = v;
    __syncthreads();
    for (int off = 1; off < 1024; off <<= 1) {
        int x = (t >= off) ? sh[t - off] : 0;
        __syncthreads();
        sh[t] += x;
        __syncthreads();
    }
    int incl = sh[t];
    if (i < M) g_rowptr[i] = incl - v;          // local exclusive
    if (t == 1023) g_bsum[blockIdx.x] = incl;   // block total
}

// Phase 2: single small block scans the block totals (exclusive, in place).
__global__ void k_scan2(int nb) {
    __shared__ int sh[64];
    int t = threadIdx.x;
    int v = (t < nb) ? g_bsum[t] : 0;
    sh[t] = v;
    __syncthreads();
    for (int off = 1; off < 64; off <<= 1) {
        int x = (t >= off) ? sh[t - off] : 0;
        __syncthreads();
        sh[t] += x;
        __syncthreads();
    }
    if (t < nb) g_bsum[t] = sh[t] - v;          // exclusive
}

// Phase 3: add block offsets, finalize rowptr + cursor.
__global__ void k_scan3(int M, int E) {
    int i = blockIdx.x * blockDim.x + threadIdx.x;
    if (i < M) {
        int v = g_rowptr[i] + g_bsum[i >> 10];
        g_rowptr[i] = v;
        g_cursor[i] = v;
    }
    if (i == 0) g_rowptr[M] = E;
}

// scatter edges into CSR slots, fusing the symmetric-normalization multiply
__global__ void k_scatter(const int* __restrict__ row, const int* __restrict__ col,
                          const float* __restrict__ val, int E) {
    int e = blockIdx.x * blockDim.x + threadIdx.x;
    if (e < E) {
        int r = row[e];
        int c = col[e];
        float nv = val[e] * g_dis[r] * g_dis[c];
        int p = atomicAdd(&g_cursor[r], 1);
        g_cw[p] = make_float2(__int_as_float(c), nv);
    }
}

// subset gather: s0[m] = features[index[m]]; srcmap[index[m]] = m
__global__ void k_gather0(const float* __restrict__ features,
                          const int* __restrict__ index, int M) {
    int i = blockIdx.x * blockDim.x + threadIdx.x;
    if (i < M * 32) {
        int m = i >> 5;
        int q = i & 31;
        int src = index[m];
        if (q == 0) g_srcmap[src] = m;
        g_s0[m * 32 + q] = ((const float4*)features)[(size_t)src * 32 + q];
    }
}

// ---------------- SpMM: warp per row, 4 gathers in flight -------------------
__global__ void __launch_bounds__(256) k_spmm(int srcsel, int M) {
    const float4* __restrict__ src = srcsel ? (const float4*)g_s1 : (const float4*)g_s0;
    float4* __restrict__ dst       = srcsel ? (float4*)g_s0       : (float4*)g_s1;
    int gw   = (blockIdx.x * blockDim.x + threadIdx.x) >> 5;
    int lane = threadIdx.x & 31;
    if (gw >= M) return;
    int e   = g_rowptr[gw];
    int end = g_rowptr[gw + 1];
    float4 acc = make_float4(0.f, 0.f, 0.f, 0.f);

    int n4 = e + ((end - e) & ~3);
    for (; e < n4; e += 4) {
        float2 p0 = __ldg(g_cw + e);
        float2 p1 = __ldg(g_cw + e + 1);
        float2 p2 = __ldg(g_cw + e + 2);
        float2 p3 = __ldg(g_cw + e + 3);
        int c0 = __float_as_int(p0.x);
        int c1 = __float_as_int(p1.x);
        int c2 = __float_as_int(p2.x);
        int c3 = __float_as_int(p3.x);
        float4 v0 = __ldg(src + c0 * 32 + lane);
        float4 v1 = __ldg(src + c1 * 32 + lane);
        float4 v2 = __ldg(src + c2 * 32 + lane);
        float4 v3 = __ldg(src + c3 * 32 + lane);
        acc.x = fmaf(p0.y, v0.x, acc.x); acc.y = fmaf(p0.y, v0.y, acc.y);
        acc.z = fmaf(p0.y, v0.z, acc.z); acc.w = fmaf(p0.y, v0.w, acc.w);
        acc.x = fmaf(p1.y, v1.x, acc.x); acc.y = fmaf(p1.y, v1.y, acc.y);
        acc.z = fmaf(p1.y, v1.z, acc.z); acc.w = fmaf(p1.y, v1.w, acc.w);
        acc.x = fmaf(p2.y, v2.x, acc.x); acc.y = fmaf(p2.y, v2.y, acc.y);
        acc.z = fmaf(p2.y, v2.z, acc.z); acc.w = fmaf(p2.y, v2.w, acc.w);
        acc.x = fmaf(p3.y, v3.x, acc.x); acc.y = fmaf(p3.y, v3.y, acc.y);
        acc.z = fmaf(p3.y, v3.z, acc.z); acc.w = fmaf(p3.y, v3.w, acc.w);
    }
    for (; e < end; e++) {
        float2 p0 = __ldg(g_cw + e);
        int c0 = __float_as_int(p0.x);
        float4 v0 = __ldg(src + c0 * 32 + lane);
        acc.x = fmaf(p0.y, v0.x, acc.x); acc.y = fmaf(p0.y, v0.y, acc.y);
        acc.z = fmaf(p0.y, v0.z, acc.z); acc.w = fmaf(p0.y, v0.w, acc.w);
    }
    dst[gw * 32 + lane] = acc;
}

// ---------------- fused MLP head --------------------------------------------
// 64 nodes per block, 256 threads. x staged in smem [64][132], weights from L1.
__device__ __forceinline__ float leaky(float v) { return v > 0.f ? v : 0.01f * v; }

__global__ void __launch_bounds__(256) k_mlp(
    const float* __restrict__ feat,
    const float* __restrict__ W1, const float* __restrict__ b1,
    const float* __restrict__ W2, const float* __restrict__ b2,
    const float* __restrict__ W3, const float* __restrict__ b3,
    const float* __restrict__ W4,
    float* __restrict__ out, int Ntot)
{
    __shared__ float xs[64 * 132];            // 33.8 KB, reused for h1/h2/h3
    float* h1s = xs;                          // [64][68]  (after sync)
    float* h2s = xs + 64 * 68;                // [64][36]
    float* h3s = xs + 64 * 68 + 64 * 36;      // [64][24]

    int t  = threadIdx.x;
    int nb = blockIdx.x * 64;

    // ---- stage x: final features row per node (s1 for propagated nodes) ----
    for (int i = t; i < 64 * 32; i += 256) {
        int n  = i >> 5;
        int c4 = i & 31;
        int gn = nb + n;
        float4 v = make_float4(0.f, 0.f, 0.f, 0.f);
        if (gn < Ntot) {
            int sm_ = g_srcmap[gn];
            const float4* src = (sm_ >= 0) ? ((const float4*)g_s1) + (size_t)sm_ * 32
                                           : ((const float4*)feat) + (size_t)gn * 32;
            v = __ldg(src + c4);
        }
        *(float4*)&xs[n * 132 + c4 * 4] = v;
    }
    __syncthreads();

    int nq = t >> 5, jl = t & 31, n0 = nq * 8;

    // ---- GEMM1: [64x128] @ W1[128x64] + b1, leaky ----
    float a0[8], a1[8];
#pragma unroll
    for (int i = 0; i < 8; i++) { a0[i] = 0.f; a1[i] = 0.f; }
#pragma unroll 4
    for (int k = 0; k < 128; k++) {
        float w0 = __ldg(W1 + k * 64 + jl);
        float w1 = __ldg(W1 + k * 64 + jl + 32);
#pragma unroll
        for (int i = 0; i < 8; i++) {
            float xv = xs[(n0 + i) * 132 + k];
            a0[i] = fmaf(xv, w0, a0[i]);
            a1[i] = fmaf(xv, w1, a1[i]);
        }
    }
    __syncthreads();   // done reading xs; h1s aliases it
    {
        float bb0 = __ldg(b1 + jl), bb1 = __ldg(b1 + jl + 32);
#pragma unroll
        for (int i = 0; i < 8; i++) {
            h1s[(n0 + i) * 68 + jl]      = leaky(a0[i] + bb0);
            h1s[(n0 + i) * 68 + jl + 32] = leaky(a1[i] + bb1);
        }
    }
    __syncthreads();

    // ---- GEMM2: [64x64] @ W2[64x32] + b2, leaky ----
    float a2[8];
#pragma unroll
    for (int i = 0; i < 8; i++) a2[i] = 0.f;
#pragma unroll 4
    for (int k = 0; k < 64; k++) {
        float w = __ldg(W2 + k * 32 + jl);
#pragma unroll
        for (int i = 0; i < 8; i++)
            a2[i] = fmaf(h1s[(n0 + i) * 68 + k], w, a2[i]);
    }
    __syncthreads();
    {
        float bb = __ldg(b2 + jl);
#pragma unroll
        for (int i = 0; i < 8; i++)
            h2s[(n0 + i) * 36 + jl] = leaky(a2[i] + bb);
    }
    __syncthreads();

    // ---- GEMM3: [64x32] @ W3[32x21] + b3, leaky ----
    float a3[8];
#pragma unroll
    for (int i = 0; i < 8; i++) a3[i] = 0.f;
    if (jl < 21) {
#pragma unroll 4
        for (int k = 0; k < 32; k++) {
            float w = __ldg(W3 + k * 21 + jl);
#pragma unroll
            for (int i = 0; i < 8; i++)
                a3[i] = fmaf(h2s[(n0 + i) * 36 + k], w, a3[i]);
        }
    }
    __syncthreads();
    if (jl < 21) {
        float bb = __ldg(b3 + jl);
#pragma unroll
        for (int i = 0; i < 8; i++)
            h3s[(n0 + i) * 24 + jl] = leaky(a3[i] + bb);
    }
    __syncthreads();

    // ---- GEMM4 + sigmoid: [64x21] @ W4[21x1] ----
    if (t < 64) {
        int gn = nb + t;
        if (gn < Ntot) {
            float s = 0.f;
#pragma unroll
            for (int k = 0; k < 21; k++)
                s = fmaf(h3s[t * 24 + k], __ldg(W4 + k), s);
            out[gn] = 1.f / (1.f + expf(-s));
        }
    }
}

// ---------------- launch -----------------------------------------------------
extern "C" void kernel_launch(void* const* d_in, const int* in_sizes, int n_in,
                              void* d_out, int out_size) {
    const float* features = (const float*)d_in[0];
    const int*   index    = (const int*)d_in[1];
    const int*   erow     = (const int*)d_in[2];
    const int*   ecol     = (const int*)d_in[3];
    const float* eval_    = (const float*)d_in[4];
    const float* W1 = (const float*)d_in[5];
    const float* b1 = (const float*)d_in[6];
    const float* W2 = (const float*)d_in[7];
    const float* b2 = (const float*)d_in[8];
    const float* W3 = (const float*)d_in[9];
    const float* b3 = (const float*)d_in[10];
    const float* W4 = (const float*)d_in[11];

    int M = in_sizes[1];
    int E = in_sizes[2];
    int N = out_size;            // [N, 1] fp32 output
    float* out = (float*)d_out;

    const int TB = 256;
    int scanBlocks = (M + 1023) / 1024;   // 49 for M=50000 (g_bsum holds 64)

    k_init   <<<(N + TB - 1) / TB, TB>>>(M, N);
    k_degcnt <<<(E + TB - 1) / TB, TB>>>(erow, eval_, E);
    k_dis    <<<(M + TB - 1) / TB, TB>>>(M);
    k_scan1  <<<scanBlocks, 1024>>>(M);
    k_scan2  <<<1, 64>>>(scanBlocks);
    k_scan3  <<<(M + TB - 1) / TB, TB>>>(M, E);
    k_scatter<<<(E + TB - 1) / TB, TB>>>(erow, ecol, eval_, E);
    k_gather0<<<(M * 32 + TB - 1) / TB, TB>>>(features, index, M);

    int spmmBlocks = (M * 32 + TB - 1) / TB;
    k_spmm<<<spmmBlocks, TB>>>(0, M);   // s0 -> s1
    k_spmm<<<spmmBlocks, TB>>>(1, M);   // s1 -> s0
    k_spmm<<<spmmBlocks, TB>>>(0, M);   // s0 -> s1  (final in s1)

    k_mlp<<<(N + 63) / 64, 256>>>(features, W1, b1, W2, b2, W3, b3, W4, out, N);
}

// round 10
// speedup vs baseline: 1.5647x; 1.1522x over previous
#include <cuda_runtime.h>
#include <cuda_fp16.h>
#include <math.h>

// Problem constants (shapes fixed by the dataset)
#define MAXM 50000
#define MAXE 600000
#define MAXN 100000
// D = 128. fp16 feature row = 256 B = 32 x uint2 (4 halves per uint2)

// ---------------- device scratch (static: no allocations allowed) -----------
__device__ float  g_deg[MAXM];
__device__ float  g_dis[MAXM];
__device__ int    g_cnt[MAXM];
__device__ int    g_rowptr[MAXM + 1];
__device__ int    g_cursor[MAXM];
__device__ int    g_bsum[64];
__device__ float2 g_cw[MAXE];        // packed (col as bits, normalized weight)
__device__ uint2  g_h0[MAXM * 32];   // fp16 features ping (12.8 MB)
__device__ uint2  g_h1[MAXM * 32];   // fp16 features pong (12.8 MB)
__device__ int    g_srcmap[MAXN];

// ---------------- preprocessing kernels ------------------------------------
__global__ void k_init(int M, int N) {
    int i = blockIdx.x * blockDim.x + threadIdx.x;
    if (i < M) { g_deg[i] = 0.f; g_cnt[i] = 0; }
    if (i < N) g_srcmap[i] = -1;
}

__global__ void k_degcnt(const int* __restrict__ row,
                         const float* __restrict__ val, int E) {
    int e = blockIdx.x * blockDim.x + threadIdx.x;
    if (e < E) {
        int r = row[e];
        atomicAdd(&g_deg[r], val[e]);
        atomicAdd(&g_cnt[r], 1);
    }
}

__global__ void k_dis(int M) {
    int i = blockIdx.x * blockDim.x + threadIdx.x;
    if (i < M) g_dis[i] = rsqrtf(g_deg[i] + 1e-8f);
}

// ---- 3-phase device-wide exclusive scan of g_cnt -> g_rowptr/g_cursor ------
__global__ void __launch_bounds__(1024) k_scan1(int M) {
    __shared__ int sh[1024];
    int t = threadIdx.x;
    int i = blockIdx.x * 1024 + t;
    int v = (i < M) ? g_cnt[i] : 0;
    sh[t] = v;
    __syncthreads();
    for (int off = 1; off < 1024; off <<= 1) {
        int x = (t >= off) ? sh[t - off] : 0;
        __syncthreads();
        sh[t] += x;
        __syncthreads();
    }
    int incl = sh[t];
    if (i < M) g_rowptr[i] = incl - v;          // local exclusive
    if (t == 1023) g_bsum[blockIdx.x] = incl;   // block total
}

__global__ void k_scan2(int nb) {
    __shared__ int sh[64];
    int t = threadIdx.x;
    int v = (t < nb) ? g_bsum[t] : 0;
    sh[t] = v;
    __syncthreads();
    for (int off = 1; off < 64; off <<= 1) {
        int x = (t >= off) ? sh[t - off] : 0;
        __syncthreads();
        sh[t] += x;
        __syncthreads();
    }
    if (t < nb) g_bsum[t] = sh[t] - v;          // exclusive
}

__global__ void k_scan3(int M, int E) {
    int i = blockIdx.x * blockDim.x + threadIdx.x;
    if (i < M) {
        int v = g_rowptr[i] + g_bsum[i >> 10];
        g_rowptr[i] = v;
        g_cursor[i] = v;
    }
    if (i == 0) g_rowptr[M] = E;
}

// scatter edges into CSR slots, fusing the symmetric-normalization multiply
__global__ void k_scatter(const int* __restrict__ row, const int* __restrict__ col,
                          const float* __restrict__ val, int E) {
    int e = blockIdx.x * blockDim.x + threadIdx.x;
    if (e < E) {
        int r = row[e];
        int c = col[e];
        float nv = val[e] * g_dis[r] * g_dis[c];
        int p = atomicAdd(&g_cursor[r], 1);
        g_cw[p] = make_float2(__int_as_float(c), nv);
    }
}

// subset gather + fp32->fp16: h0[m] = half(features[index[m]]); srcmap set
__global__ void k_gather0(const float* __restrict__ features,
                          const int* __restrict__ index, int M) {
    int i = blockIdx.x * blockDim.x + threadIdx.x;
    if (i < M * 32) {
        int m = i >> 5;
        int q = i & 31;
        int src = index[m];
        if (q == 0) g_srcmap[src] = m;
        float4 v = ((const float4*)features)[(size_t)src * 32 + q];
        __half2 lo = __floats2half2_rn(v.x, v.y);
        __half2 hi = __floats2half2_rn(v.z, v.w);
        uint2 o;
        *(__half2*)&o.x = lo;
        *(__half2*)&o.y = hi;
        g_h0[m * 32 + q] = o;
    }
}

// ---------------- SpMM: warp per row, fp16 gathers, fp32 accumulate ---------
__global__ void __launch_bounds__(256) k_spmm(int srcsel, int M) {
    const uint2* __restrict__ src = srcsel ? (const uint2*)g_h1 : (const uint2*)g_h0;
    uint2* __restrict__ dst       = srcsel ? (uint2*)g_h0       : (uint2*)g_h1;
    int gw   = (blockIdx.x * blockDim.x + threadIdx.x) >> 5;
    int lane = threadIdx.x & 31;
    if (gw >= M) return;
    int e   = g_rowptr[gw];
    int end = g_rowptr[gw + 1];
    float4 acc = make_float4(0.f, 0.f, 0.f, 0.f);

    int n4 = e + ((end - e) & ~3);
    for (; e < n4; e += 4) {
        float2 p0 = __ldg(g_cw + e);
        float2 p1 = __ldg(g_cw + e + 1);
        float2 p2 = __ldg(g_cw + e + 2);
        float2 p3 = __ldg(g_cw + e + 3);
        int c0 = __float_as_int(p0.x);
        int c1 = __float_as_int(p1.x);
        int c2 = __float_as_int(p2.x);
        int c3 = __float_as_int(p3.x);
        uint2 v0 = __ldg(src + c0 * 32 + lane);
        uint2 v1 = __ldg(src + c1 * 32 + lane);
        uint2 v2 = __ldg(src + c2 * 32 + lane);
        uint2 v3 = __ldg(src + c3 * 32 + lane);
        float2 a, b;
        a = __half22float2(*(__half2*)&v0.x); b = __half22float2(*(__half2*)&v0.y);
        acc.x = fmaf(p0.y, a.x, acc.x); acc.y = fmaf(p0.y, a.y, acc.y);
        acc.z = fmaf(p0.y, b.x, acc.z); acc.w = fmaf(p0.y, b.y, acc.w);
        a = __half22float2(*(__half2*)&v1.x); b = __half22float2(*(__half2*)&v1.y);
        acc.x = fmaf(p1.y, a.x, acc.x); acc.y = fmaf(p1.y, a.y, acc.y);
        acc.z = fmaf(p1.y, b.x, acc.z); acc.w = fmaf(p1.y, b.y, acc.w);
        a = __half22float2(*(__half2*)&v2.x); b = __half22float2(*(__half2*)&v2.y);
        acc.x = fmaf(p2.y, a.x, acc.x); acc.y = fmaf(p2.y, a.y, acc.y);
        acc.z = fmaf(p2.y, b.x, acc.z); acc.w = fmaf(p2.y, b.y, acc.w);
        a = __half22float2(*(__half2*)&v3.x); b = __half22float2(*(__half2*)&v3.y);
        acc.x = fmaf(p3.y, a.x, acc.x); acc.y = fmaf(p3.y, a.y, acc.y);
        acc.z = fmaf(p3.y, b.x, acc.z); acc.w = fmaf(p3.y, b.y, acc.w);
    }
    for (; e < end; e++) {
        float2 p0 = __ldg(g_cw + e);
        int c0 = __float_as_int(p0.x);
        uint2 v0 = __ldg(src + c0 * 32 + lane);
        float2 a = __half22float2(*(__half2*)&v0.x);
        float2 b = __half22float2(*(__half2*)&v0.y);
        acc.x = fmaf(p0.y, a.x, acc.x); acc.y = fmaf(p0.y, a.y, acc.y);
        acc.z = fmaf(p0.y, b.x, acc.z); acc.w = fmaf(p0.y, b.y, acc.w);
    }
    __half2 lo = __floats2half2_rn(acc.x, acc.y);
    __half2 hi = __floats2half2_rn(acc.z, acc.w);
    uint2 o;
    *(__half2*)&o.x = lo;
    *(__half2*)&o.y = hi;
    dst[gw * 32 + lane] = o;
}

// ---------------- fused MLP head --------------------------------------------
// 64 nodes per block, 256 threads. x staged in smem [64][132], weights from L1.
__device__ __forceinline__ float leaky(float v) { return v > 0.f ? v : 0.01f * v; }

__global__ void __launch_bounds__(256) k_mlp(
    const float* __restrict__ feat,
    const float* __restrict__ W1, const float* __restrict__ b1,
    const float* __restrict__ W2, const float* __restrict__ b2,
    const float* __restrict__ W3, const float* __restrict__ b3,
    const float* __restrict__ W4,
    float* __restrict__ out, int Ntot)
{
    __shared__ float xs[64 * 132];            // 33.8 KB, reused for h1/h2/h3
    float* h1s = xs;                          // [64][68]  (after sync)
    float* h2s = xs + 64 * 68;                // [64][36]
    float* h3s = xs + 64 * 68 + 64 * 36;      // [64][24]

    int t  = threadIdx.x;
    int nb = blockIdx.x * 64;

    // ---- stage x: final features row per node (g_h1 for propagated nodes) --
    for (int i = t; i < 64 * 32; i += 256) {
        int n  = i >> 5;
        int c4 = i & 31;
        int gn = nb + n;
        float4 v = make_float4(0.f, 0.f, 0.f, 0.f);
        if (gn < Ntot) {
            int sm_ = g_srcmap[gn];
            if (sm_ >= 0) {
                uint2 h = __ldg(((const uint2*)g_h1) + (size_t)sm_ * 32 + c4);
                float2 a = __half22float2(*(__half2*)&h.x);
                float2 b = __half22float2(*(__half2*)&h.y);
                v = make_float4(a.x, a.y, b.x, b.y);
            } else {
                v = __ldg(((const float4*)feat) + (size_t)gn * 32 + c4);
            }
        }
        *(float4*)&xs[n * 132 + c4 * 4] = v;
    }
    __syncthreads();

    int nq = t >> 5, jl = t & 31, n0 = nq * 8;

    // ---- GEMM1: [64x128] @ W1[128x64] + b1, leaky ----
    float a0[8], a1[8];
#pragma unroll
    for (int i = 0; i < 8; i++) { a0[i] = 0.f; a1[i] = 0.f; }
#pragma unroll 4
    for (int k = 0; k < 128; k++) {
        float w0 = __ldg(W1 + k * 64 + jl);
        float w1 = __ldg(W1 + k * 64 + jl + 32);
#pragma unroll
        for (int i = 0; i < 8; i++) {
            float xv = xs[(n0 + i) * 132 + k];
            a0[i] = fmaf(xv, w0, a0[i]);
            a1[i] = fmaf(xv, w1, a1[i]);
        }
    }
    __syncthreads();   // done reading xs; h1s aliases it
    {
        float bb0 = __ldg(b1 + jl), bb1 = __ldg(b1 + jl + 32);
#pragma unroll
        for (int i = 0; i < 8; i++) {
            h1s[(n0 + i) * 68 + jl]      = leaky(a0[i] + bb0);
            h1s[(n0 + i) * 68 + jl + 32] = leaky(a1[i] + bb1);
        }
    }
    __syncthreads();

    // ---- GEMM2: [64x64] @ W2[64x32] + b2, leaky ----
    float a2[8];
#pragma unroll
    for (int i = 0; i < 8; i++) a2[i] = 0.f;
#pragma unroll 4
    for (int k = 0; k < 64; k++) {
        float w = __ldg(W2 + k * 32 + jl);
#pragma unroll
        for (int i = 0; i < 8; i++)
            a2[i] = fmaf(h1s[(n0 + i) * 68 + k], w, a2[i]);
    }
    __syncthreads();
    {
        float bb = __ldg(b2 + jl);
#pragma unroll
        for (int i = 0; i < 8; i++)
            h2s[(n0 + i) * 36 + jl] = leaky(a2[i] + bb);
    }
    __syncthreads();

    // ---- GEMM3: [64x32] @ W3[32x21] + b3, leaky ----
    float a3[8];
#pragma unroll
    for (int i = 0; i < 8; i++) a3[i] = 0.f;
    if (jl < 21) {
#pragma unroll 4
        for (int k = 0; k < 32; k++) {
            float w = __ldg(W3 + k * 21 + jl);
#pragma unroll
            for (int i = 0; i < 8; i++)
                a3[i] = fmaf(h2s[(n0 + i) * 36 + k], w, a3[i]);
        }
    }
    __syncthreads();
    if (jl < 21) {
        float bb = __ldg(b3 + jl);
#pragma unroll
        for (int i = 0; i < 8; i++)
            h3s[(n0 + i) * 24 + jl] = leaky(a3[i] + bb);
    }
    __syncthreads();

    // ---- GEMM4 + sigmoid: [64x21] @ W4[21x1] ----
    if (t < 64) {
        int gn = nb + t;
        if (gn < Ntot) {
            float s = 0.f;
#pragma unroll
            for (int k = 0; k < 21; k++)
                s = fmaf(h3s[t * 24 + k], __ldg(W4 + k), s);
            out[gn] = 1.f / (1.f + expf(-s));
        }
    }
}

// ---------------- launch -----------------------------------------------------
extern "C" void kernel_launch(void* const* d_in, const int* in_sizes, int n_in,
                              void* d_out, int out_size) {
    const float* features = (const float*)d_in[0];
    const int*   index    = (const int*)d_in[1];
    const int*   erow     = (const int*)d_in[2];
    const int*   ecol     = (const int*)d_in[3];
    const float* eval_    = (const float*)d_in[4];
    const float* W1 = (const float*)d_in[5];
    const float* b1 = (const float*)d_in[6];
    const float* W2 = (const float*)d_in[7];
    const float* b2 = (const float*)d_in[8];
    const float* W3 = (const float*)d_in[9];
    const float* b3 = (const float*)d_in[10];
    const float* W4 = (const float*)d_in[11];

    int M = in_sizes[1];
    int E = in_sizes[2];
    int N = out_size;            // [N, 1] fp32 output
    float* out = (float*)d_out;

    const int TB = 256;
    int scanBlocks = (M + 1023) / 1024;   // 49 for M=50000 (g_bsum holds 64)

    k_init   <<<(N + TB - 1) / TB, TB>>>(M, N);
    k_degcnt <<<(E + TB - 1) / TB, TB>>>(erow, eval_, E);
    k_dis    <<<(M + TB - 1) / TB, TB>>>(M);
    k_scan1  <<<scanBlocks, 1024>>>(M);
    k_scan2  <<<1, 64>>>(scanBlocks);
    k_scan3  <<<(M + TB - 1) / TB, TB>>>(M, E);
    k_scatter<<<(E + TB - 1) / TB, TB>>>(erow, ecol, eval_, E);
    k_gather0<<<(M * 32 + TB - 1) / TB, TB>>>(features, index, M);

    int spmmBlocks = (M * 32 + TB - 1) / TB;
    k_spmm<<<spmmBlocks, TB>>>(0, M);   // h0 -> h1
    k_spmm<<<spmmBlocks, TB>>>(1, M);   // h1 -> h0
    k_spmm<<<spmmBlocks, TB>>>(0, M);   // h0 -> h1  (final in h1)

    k_mlp<<<(N + 63) / 64, 256>>>(features, W1, b1, W2, b2, W3, b3, W4, out, N);
}

// round 14
// speedup vs baseline: 1.5700x; 1.0034x over previous
#include <cuda_runtime.h>
#include <cuda_fp16.h>
#include <math.h>

// Problem constants (shapes fixed by the dataset)
#define MAXM 50000
#define MAXE 600000
#define MAXN 100000
// D = 128. fp16 feature row = 256 B = 16 x uint4

// ---------------- device scratch (static: no allocations allowed) -----------
__device__ float  g_deg[MAXM];
__device__ float  g_dis[MAXM];
__device__ int    g_cnt[MAXM];
__device__ int    g_rowptr[MAXM + 1];
__device__ int    g_cursor[MAXM];
__device__ int    g_bsum[64];
__device__ float2 g_cw[MAXE];        // packed (col as bits, normalized weight)
__device__ uint4  g_h0[MAXM * 16];   // fp16 features ping (12.8 MB)
__device__ uint4  g_h1[MAXM * 16];   // fp16 features pong (12.8 MB)
__device__ int    g_srcmap[MAXN];    // zero-init: 0 = not propagated, else m+1

// ---------------- f32x2 helpers ---------------------------------------------
__device__ __forceinline__ unsigned long long packf2(float lo, float hi) {
    unsigned long long r;
    asm("mov.b64 %0, {%1, %2};" : "=l"(r) : "f"(lo), "f"(hi));
    return r;
}
__device__ __forceinline__ void unpackf2(unsigned long long v, float& lo, float& hi) {
    asm("mov.b64 {%0, %1}, %2;" : "=f"(lo), "=f"(hi) : "l"(v));
}
__device__ __forceinline__ unsigned long long fma2(unsigned long long a,
                                                   unsigned long long b,
                                                   unsigned long long c) {
    unsigned long long d;
    asm("fma.rn.f32x2 %0, %1, %2, %3;" : "=l"(d) : "l"(a), "l"(b), "l"(c));
    return d;
}

// ---------------- preprocessing kernels ------------------------------------
__global__ void k_init(int M) {
    int i = blockIdx.x * blockDim.x + threadIdx.x;
    if (i < M) { g_deg[i] = 0.f; g_cnt[i] = 0; }
}

__global__ void k_degcnt(const int* __restrict__ row,
                         const float* __restrict__ val, int E) {
    int e = blockIdx.x * blockDim.x + threadIdx.x;
    if (e < E) {
        int r = row[e];
        atomicAdd(&g_deg[r], val[e]);
        atomicAdd(&g_cnt[r], 1);
    }
}

// Phase 1 scan (+ fused d^-1/2): per-block local exclusive scan of g_cnt.
__global__ void __launch_bounds__(1024) k_scan1(int M) {
    __shared__ int sh[1024];
    int t = threadIdx.x;
    int i = blockIdx.x * 1024 + t;
    if (i < M) g_dis[i] = rsqrtf(g_deg[i] + 1e-8f);
    int v = (i < M) ? g_cnt[i] : 0;
    sh[t] = v;
    __syncthreads();
    for (int off = 1; off < 1024; off <<= 1) {
        int x = (t >= off) ? sh[t - off] : 0;
        __syncthreads();
        sh[t] += x;
        __syncthreads();
    }
    int incl = sh[t];
    if (i < M) g_rowptr[i] = incl - v;          // local exclusive
    if (t == 1023) g_bsum[blockIdx.x] = incl;   // block total
}

// Phase 2+3 fused: each block redundantly scans the block totals in smem,
// then finalizes rowptr/cursor for its slice.
__global__ void k_scan3(int M, int E, int nb) {
    __shared__ int sh[64];
    int t = threadIdx.x;
    if (t < 64) sh[t] = (t < nb) ? g_bsum[t] : 0;
    __syncthreads();
    if (t == 0) {
        int s = 0;
        for (int j = 0; j < nb; j++) { int v = sh[j]; sh[j] = s; s += v; }
    }
    __syncthreads();
    int i = blockIdx.x * blockDim.x + t;
    if (i < M) {
        int v = g_rowptr[i] + sh[i >> 10];
        g_rowptr[i] = v;
        g_cursor[i] = v;
    }
    if (i == 0) g_rowptr[M] = E;
}

// scatter edges into CSR slots, fusing the symmetric-normalization multiply
__global__ void k_scatter(const int* __restrict__ row, const int* __restrict__ col,
                          const float* __restrict__ val, int E) {
    int e = blockIdx.x * blockDim.x + threadIdx.x;
    if (e < E) {
        int r = row[e];
        int c = col[e];
        float nv = val[e] * g_dis[r] * g_dis[c];
        int p = atomicAdd(&g_cursor[r], 1);
        g_cw[p] = make_float2(__int_as_float(c), nv);
    }
}

// subset gather + fp32->fp16: h0[m] = half(features[index[m]]); srcmap = m+1
__global__ void k_gather0(const float* __restrict__ features,
                          const int* __restrict__ index, int M) {
    int i = blockIdx.x * blockDim.x + threadIdx.x;
    if (i < M * 32) {
        int m = i >> 5;
        int q = i & 31;
        int src = index[m];
        if (q == 0) g_srcmap[src] = m + 1;
        float4 v = ((const float4*)features)[(size_t)src * 32 + q];
        __half2 lo = __floats2half2_rn(v.x, v.y);
        __half2 hi = __floats2half2_rn(v.z, v.w);
        uint2 o;
        *(__half2*)&o.x = lo;
        *(__half2*)&o.y = hi;
        ((uint2*)g_h0)[m * 32 + q] = o;
    }
}

// ---------------- SpMM: 2 rows per warp (16 lanes x 16B), fp32 accum --------
__device__ __forceinline__ void acc8(float* acc, uint4 v, float wgt) {
    float2 f;
    f = __half22float2(*(__half2*)&v.x);
    acc[0] = fmaf(wgt, f.x, acc[0]); acc[1] = fmaf(wgt, f.y, acc[1]);
    f = __half22float2(*(__half2*)&v.y);
    acc[2] = fmaf(wgt, f.x, acc[2]); acc[3] = fmaf(wgt, f.y, acc[3]);
    f = __half22float2(*(__half2*)&v.z);
    acc[4] = fmaf(wgt, f.x, acc[4]); acc[5] = fmaf(wgt, f.y, acc[5]);
    f = __half22float2(*(__half2*)&v.w);
    acc[6] = fmaf(wgt, f.x, acc[6]); acc[7] = fmaf(wgt, f.y, acc[7]);
}

__global__ void __launch_bounds__(256) k_spmm(int srcsel, int M) {
    const uint4* __restrict__ src = srcsel ? (const uint4*)g_h1 : (const uint4*)g_h0;
    uint4* __restrict__ dst       = srcsel ? (uint4*)g_h0       : (uint4*)g_h1;
    int gw   = (blockIdx.x * blockDim.x + threadIdx.x) >> 5;
    int half = (threadIdx.x >> 4) & 1;
    int l    = threadIdx.x & 15;
    int r    = gw * 2 + half;
    int e = 0, end = 0;
    if (r < M) { e = g_rowptr[r]; end = g_rowptr[r + 1]; }
    float acc[8] = {0.f, 0.f, 0.f, 0.f, 0.f, 0.f, 0.f, 0.f};

    for (; e + 4 <= end; e += 4) {
        float2 p0 = __ldg(g_cw + e);
        float2 p1 = __ldg(g_cw + e + 1);
        float2 p2 = __ldg(g_cw + e + 2);
        float2 p3 = __ldg(g_cw + e + 3);
        uint4 v0 = __ldg(src + __float_as_int(p0.x) * 16 + l);
        uint4 v1 = __ldg(src + __float_as_int(p1.x) * 16 + l);
        uint4 v2 = __ldg(src + __float_as_int(p2.x) * 16 + l);
        uint4 v3 = __ldg(src + __float_as_int(p3.x) * 16 + l);
        acc8(acc, v0, p0.y); acc8(acc, v1, p1.y);
        acc8(acc, v2, p2.y); acc8(acc, v3, p3.y);
    }
    for (; e < end; e++) {
        float2 p0 = __ldg(g_cw + e);
        uint4 v0 = __ldg(src + __float_as_int(p0.x) * 16 + l);
        acc8(acc, v0, p0.y);
    }
    if (r < M) {
        uint4 o;
        *(__half2*)&o.x = __floats2half2_rn(acc[0], acc[1]);
        *(__half2*)&o.y = __floats2half2_rn(acc[2], acc[3]);
        *(__half2*)&o.z = __floats2half2_rn(acc[4], acc[5]);
        *(__half2*)&o.w = __floats2half2_rn(acc[6], acc[7]);
        dst[r * 16 + l] = o;
    }
}

// ---------------- fused MLP head (f32x2-packed GEMMs) -----------------------
// 64 nodes per block, 256 threads. x staged TRANSPOSED: xt[k*66 + node].
__device__ __forceinline__ float leaky(float v) { return v > 0.f ? v : 0.01f * v; }

__global__ void __launch_bounds__(256) k_mlp(
    const float* __restrict__ feat,
    const float* __restrict__ W1, const float* __restrict__ b1,
    const float* __restrict__ W2, const float* __restrict__ b2,
    const float* __restrict__ W3, const float* __restrict__ b3,
    const float* __restrict__ W4,
    float* __restrict__ out, int Ntot)
{
    __shared__ float xs[128 * 66];            // 33.8 KB; reused after GEMM1
    float* xt  = xs;                          // [128][66]  x transposed
    float* h1t = xs;                          // [64][66]   (aliases xt after sync)
    float* h2t = xs + 64 * 66;                // [32][66]
    float* h3t = xs + 64 * 66 + 32 * 66;      // [21][66]

    int t  = threadIdx.x;
    int nb = blockIdx.x * 64;

    // ---- stage x transposed: xt[k][n] ----
    for (int i = t; i < 64 * 32; i += 256) {
        int n  = i >> 5;
        int c4 = i & 31;
        int gn = nb + n;
        float4 v = make_float4(0.f, 0.f, 0.f, 0.f);
        if (gn < Ntot) {
            int sm_ = g_srcmap[gn];
            if (sm_ > 0) {
                uint2 h = __ldg(((const uint2*)g_h1) + (size_t)(sm_ - 1) * 32 + c4);
                float2 a = __half22float2(*(__half2*)&h.x);
                float2 b = __half22float2(*(__half2*)&h.y);
                v = make_float4(a.x, a.y, b.x, b.y);
            } else {
                v = __ldg(((const float4*)feat) + (size_t)gn * 32 + c4);
            }
        }
        int k0 = c4 * 4;
        xt[(k0 + 0) * 66 + n] = v.x;
        xt[(k0 + 1) * 66 + n] = v.y;
        xt[(k0 + 2) * 66 + n] = v.z;
        xt[(k0 + 3) * 66 + n] = v.w;
    }
    __syncthreads();

    int jl = t & 31, nq = t >> 5, n0 = nq * 8;

    // ---- GEMM1: [64x128] @ W1[128x64] + b1, leaky (f32x2) ----
    unsigned long long a0p[4], a1p[4];
#pragma unroll
    for (int i = 0; i < 4; i++) { a0p[i] = 0ull; a1p[i] = 0ull; }
#pragma unroll 2
    for (int k = 0; k < 128; k++) {
        float w0 = __ldg(W1 + k * 64 + jl);
        float w1 = __ldg(W1 + k * 64 + jl + 32);
        unsigned long long w00 = packf2(w0, w0);
        unsigned long long w11 = packf2(w1, w1);
        const float* xr = &xt[k * 66 + n0];
#pragma unroll
        for (int i = 0; i < 4; i++) {
            unsigned long long xx = *(const unsigned long long*)(xr + 2 * i);
            a0p[i] = fma2(xx, w00, a0p[i]);
            a1p[i] = fma2(xx, w11, a1p[i]);
        }
    }
    __syncthreads();   // all warps done reading xt; h1t aliases it
    {
        float bb0 = __ldg(b1 + jl), bb1 = __ldg(b1 + jl + 32);
#pragma unroll
        for (int i = 0; i < 4; i++) {
            float lo, hi;
            unpackf2(a0p[i], lo, hi);
            h1t[jl * 66 + n0 + 2 * i]     = leaky(lo + bb0);
            h1t[jl * 66 + n0 + 2 * i + 1] = leaky(hi + bb0);
            unpackf2(a1p[i], lo, hi);
            h1t[(jl + 32) * 66 + n0 + 2 * i]     = leaky(lo + bb1);
            h1t[(jl + 32) * 66 + n0 + 2 * i + 1] = leaky(hi + bb1);
        }
    }
    __syncthreads();

    // ---- GEMM2: [64x64] @ W2[64x32] + b2, leaky (f32x2) ----
    unsigned long long a2p[4];
#pragma unroll
    for (int i = 0; i < 4; i++) a2p[i] = 0ull;
#pragma unroll 4
    for (int k = 0; k < 64; k++) {
        float w = __ldg(W2 + k * 32 + jl);
        unsigned long long ww = packf2(w, w);
        const float* hr = &h1t[k * 66 + n0];
#pragma unroll
        for (int i = 0; i < 4; i++) {
            unsigned long long xx = *(const unsigned long long*)(hr + 2 * i);
            a2p[i] = fma2(xx, ww, a2p[i]);
        }
    }
    {
        float bb = __ldg(b2 + jl);
#pragma unroll
        for (int i = 0; i < 4; i++) {
            float lo, hi;
            unpackf2(a2p[i], lo, hi);
            h2t[jl * 66 + n0 + 2 * i]     = leaky(lo + bb);
            h2t[jl * 66 + n0 + 2 * i + 1] = leaky(hi + bb);
        }
    }
    __syncthreads();

    // ---- GEMM3: [64x32] @ W3[32x21] + b3, leaky (f32x2) ----
    if (jl < 21) {
        unsigned long long a3p[4];
#pragma unroll
        for (int i = 0; i < 4; i++) a3p[i] = 0ull;
#pragma unroll 4
        for (int k = 0; k < 32; k++) {
            float w = __ldg(W3 + k * 21 + jl);
            unsigned long long ww = packf2(w, w);
            const float* hr = &h2t[k * 66 + n0];
#pragma unroll
            for (int i = 0; i < 4; i++) {
                unsigned long long xx = *(const unsigned long long*)(hr + 2 * i);
                a3p[i] = fma2(xx, ww, a3p[i]);
            }
        }
        float bb = __ldg(b3 + jl);
#pragma unroll
        for (int i = 0; i < 4; i++) {
            float lo, hi;
            unpackf2(a3p[i], lo, hi);
            h3t[jl * 66 + n0 + 2 * i]     = leaky(lo + bb);
            h3t[jl * 66 + n0 + 2 * i + 1] = leaky(hi + bb);
        }
    }
    __syncthreads();

    // ---- GEMM4 + sigmoid: [64x21] @ W4[21x1] ----
    if (t < 64) {
        int gn = nb + t;
        if (gn < Ntot) {
            float s = 0.f;
#pragma unroll
            for (int k = 0; k < 21; k++)
                s = fmaf(h3t[k * 66 + t], __ldg(W4 + k), s);
            out[gn] = 1.f / (1.f + expf(-s));
        }
    }
}

// ---------------- launch -----------------------------------------------------
extern "C" void kernel_launch(void* const* d_in, const int* in_sizes, int n_in,
                              void* d_out, int out_size) {
    const float* features = (const float*)d_in[0];
    const int*   index    = (const int*)d_in[1];
    const int*   erow     = (const int*)d_in[2];
    const int*   ecol     = (const int*)d_in[3];
    const float* eval_    = (const float*)d_in[4];
    const float* W1 = (const float*)d_in[5];
    const float* b1 = (const float*)d_in[6];
    const float* W2 = (const float*)d_in[7];
    const float* b2 = (const float*)d_in[8];
    const float* W3 = (const float*)d_in[9];
    const float* b3 = (const float*)d_in[10];
    const float* W4 = (const float*)d_in[11];

    int M = in_sizes[1];
    int E = in_sizes[2];
    int N = out_size;            // [N, 1] fp32 output
    float* out = (float*)d_out;

    const int TB = 256;
    int scanBlocks = (M + 1023) / 1024;   // 49 for M=50000 (g_bsum holds 64)

    k_init   <<<(M + TB - 1) / TB, TB>>>(M);
    k_degcnt <<<(E + TB - 1) / TB, TB>>>(erow, eval_, E);
    k_scan1  <<<scanBlocks, 1024>>>(M);
    k_scan3  <<<(M + TB - 1) / TB, TB>>>(M, E, scanBlocks);
    k_scatter<<<(E + TB - 1) / TB, TB>>>(erow, ecol, eval_, E);
    k_gather0<<<(M * 32 + TB - 1) / TB, TB>>>(features, index, M);

    int spmmBlocks = (M + 15) / 16;       // 2 rows per warp, 8 warps per block
    k_spmm<<<spmmBlocks, TB>>>(0, M);     // h0 -> h1
    k_spmm<<<spmmBlocks, TB>>>(1, M);     // h1 -> h0
    k_spmm<<<spmmBlocks, TB>>>(0, M);     // h0 -> h1  (final in h1)

    k_mlp<<<(N + 63) / 64, 256>>>(features, W1, b1, W2, b2, W3, b3, W4, out, N);
}

// round 15
// speedup vs baseline: 2.3785x; 1.5150x over previous
#include <cuda_runtime.h>
#include <cuda_fp16.h>
#include <math.h>

// Problem constants (shapes fixed by the dataset)
#define MAXM 50000
#define MAXE 600000
#define MAXN 100000
// D = 128. fp16 feature row = 256 B = 16 x uint4

// ---------------- device scratch (static: no allocations allowed) -----------
__device__ float  g_deg[MAXM];
__device__ float  g_dis[MAXM];
__device__ int    g_cnt[MAXM];
__device__ int    g_rowptr[MAXM + 1];
__device__ int    g_cursor[MAXM];
__device__ int    g_bsum[64];
__device__ float2 g_cw[MAXE];        // packed (col as bits, normalized weight)
__device__ uint4  g_h0[MAXM * 16];   // fp16 features ping (12.8 MB)
__device__ uint4  g_h1[MAXM * 16];   // fp16 features pong (12.8 MB)
__device__ int    g_srcmap[MAXN];    // zero-init: 0 = not propagated, else m+1

// fp16 transposed weights (converted per-launch in k_init)
__device__ __half g_w1t[64 * 136];   // W1t[j][k], j<64, k<128, stride 136
__device__ __half g_w2t[32 * 72];    // W2t[j][k], j<32, k<64,  stride 72
__device__ __half g_w3t[24 * 40];    // W3t[j][k], j<24 (21 real), k<32, stride 40

// ---------------- preprocessing kernels ------------------------------------
__global__ void k_init(int M,
                       const float* __restrict__ W1,
                       const float* __restrict__ W2,
                       const float* __restrict__ W3) {
    int i = blockIdx.x * blockDim.x + threadIdx.x;
    if (i < M) { g_deg[i] = 0.f; g_cnt[i] = 0; }
    // fp16 transposed weight conversion (11008 threads' worth)
    if (i < 8192) {                       // W1: j = i>>7, k = i&127
        int j = i >> 7, k = i & 127;
        g_w1t[j * 136 + k] = __float2half(W1[k * 64 + j]);
    } else if (i < 8192 + 2048) {         // W2
        int i2 = i - 8192;
        int j = i2 >> 6, k = i2 & 63;
        g_w2t[j * 72 + k] = __float2half(W2[k * 32 + j]);
    } else if (i < 8192 + 2048 + 768) {   // W3 (pad j 21..23 with zeros)
        int i3 = i - 8192 - 2048;
        int j = i3 >> 5, k = i3 & 31;
        g_w3t[j * 40 + k] = (j < 21) ? __float2half(W3[k * 21 + j]) : __half(0.f);
    }
}

__global__ void k_degcnt(const int* __restrict__ row,
                         const float* __restrict__ val, int E) {
    int e = blockIdx.x * blockDim.x + threadIdx.x;
    if (e < E) {
        int r = row[e];
        atomicAdd(&g_deg[r], val[e]);
        atomicAdd(&g_cnt[r], 1);
    }
}

// Phase 1 scan (+ fused d^-1/2): per-block local exclusive scan of g_cnt.
__global__ void __launch_bounds__(1024) k_scan1(int M) {
    __shared__ int sh[1024];
    int t = threadIdx.x;
    int i = blockIdx.x * 1024 + t;
    if (i < M) g_dis[i] = rsqrtf(g_deg[i] + 1e-8f);
    int v = (i < M) ? g_cnt[i] : 0;
    sh[t] = v;
    __syncthreads();
    for (int off = 1; off < 1024; off <<= 1) {
        int x = (t >= off) ? sh[t - off] : 0;
        __syncthreads();
        sh[t] += x;
        __syncthreads();
    }
    int incl = sh[t];
    if (i < M) g_rowptr[i] = incl - v;          // local exclusive
    if (t == 1023) g_bsum[blockIdx.x] = incl;   // block total
}

// Phase 2+3 fused: each block redundantly scans the block totals in smem,
// then finalizes rowptr/cursor for its slice.
__global__ void k_scan3(int M, int E, int nb) {
    __shared__ int sh[64];
    int t = threadIdx.x;
    if (t < 64) sh[t] = (t < nb) ? g_bsum[t] : 0;
    __syncthreads();
    if (t == 0) {
        int s = 0;
        for (int j = 0; j < nb; j++) { int v = sh[j]; sh[j] = s; s += v; }
    }
    __syncthreads();
    int i = blockIdx.x * blockDim.x + t;
    if (i < M) {
        int v = g_rowptr[i] + sh[i >> 10];
        g_rowptr[i] = v;
        g_cursor[i] = v;
    }
    if (i == 0) g_rowptr[M] = E;
}

// scatter edges into CSR slots, fusing the symmetric-normalization multiply
__global__ void k_scatter(const int* __restrict__ row, const int* __restrict__ col,
                          const float* __restrict__ val, int E) {
    int e = blockIdx.x * blockDim.x + threadIdx.x;
    if (e < E) {
        int r = row[e];
        int c = col[e];
        float nv = val[e] * g_dis[r] * g_dis[c];
        int p = atomicAdd(&g_cursor[r], 1);
        g_cw[p] = make_float2(__int_as_float(c), nv);
    }
}

// subset gather + fp32->fp16: h0[m] = half(features[index[m]]); srcmap = m+1
__global__ void k_gather0(const float* __restrict__ features,
                          const int* __restrict__ index, int M) {
    int i = blockIdx.x * blockDim.x + threadIdx.x;
    if (i < M * 32) {
        int m = i >> 5;
        int q = i & 31;
        int src = index[m];
        if (q == 0) g_srcmap[src] = m + 1;
        float4 v = ((const float4*)features)[(size_t)src * 32 + q];
        __half2 lo = __floats2half2_rn(v.x, v.y);
        __half2 hi = __floats2half2_rn(v.z, v.w);
        uint2 o;
        *(__half2*)&o.x = lo;
        *(__half2*)&o.y = hi;
        ((uint2*)g_h0)[m * 32 + q] = o;
    }
}

// ---------------- SpMM: 2 rows per warp (16 lanes x 16B), fp32 accum --------
__device__ __forceinline__ void acc8(float* acc, uint4 v, float wgt) {
    float2 f;
    f = __half22float2(*(__half2*)&v.x);
    acc[0] = fmaf(wgt, f.x, acc[0]); acc[1] = fmaf(wgt, f.y, acc[1]);
    f = __half22float2(*(__half2*)&v.y);
    acc[2] = fmaf(wgt, f.x, acc[2]); acc[3] = fmaf(wgt, f.y, acc[3]);
    f = __half22float2(*(__half2*)&v.z);
    acc[4] = fmaf(wgt, f.x, acc[4]); acc[5] = fmaf(wgt, f.y, acc[5]);
    f = __half22float2(*(__half2*)&v.w);
    acc[6] = fmaf(wgt, f.x, acc[6]); acc[7] = fmaf(wgt, f.y, acc[7]);
}

__global__ void __launch_bounds__(256) k_spmm(int srcsel, int M) {
    const uint4* __restrict__ src = srcsel ? (const uint4*)g_h1 : (const uint4*)g_h0;
    uint4* __restrict__ dst       = srcsel ? (uint4*)g_h0       : (uint4*)g_h1;
    int gw   = (blockIdx.x * blockDim.x + threadIdx.x) >> 5;
    int half = (threadIdx.x >> 4) & 1;
    int l    = threadIdx.x & 15;
    int r    = gw * 2 + half;
    int e = 0, end = 0;
    if (r < M) { e = g_rowptr[r]; end = g_rowptr[r + 1]; }
    float acc[8] = {0.f, 0.f, 0.f, 0.f, 0.f, 0.f, 0.f, 0.f};

    for (; e + 4 <= end; e += 4) {
        float2 p0 = __ldg(g_cw + e);
        float2 p1 = __ldg(g_cw + e + 1);
        float2 p2 = __ldg(g_cw + e + 2);
        float2 p3 = __ldg(g_cw + e + 3);
        uint4 v0 = __ldg(src + __float_as_int(p0.x) * 16 + l);
        uint4 v1 = __ldg(src + __float_as_int(p1.x) * 16 + l);
        uint4 v2 = __ldg(src + __float_as_int(p2.x) * 16 + l);
        uint4 v3 = __ldg(src + __float_as_int(p3.x) * 16 + l);
        acc8(acc, v0, p0.y); acc8(acc, v1, p1.y);
        acc8(acc, v2, p2.y); acc8(acc, v3, p3.y);
    }
    for (; e < end; e++) {
        float2 p0 = __ldg(g_cw + e);
        uint4 v0 = __ldg(src + __float_as_int(p0.x) * 16 + l);
        acc8(acc, v0, p0.y);
    }
    if (r < M) {
        uint4 o;
        *(__half2*)&o.x = __floats2half2_rn(acc[0], acc[1]);
        *(__half2*)&o.y = __floats2half2_rn(acc[2], acc[3]);
        *(__half2*)&o.z = __floats2half2_rn(acc[4], acc[5]);
        *(__half2*)&o.w = __floats2half2_rn(acc[6], acc[7]);
        dst[r * 16 + l] = o;
    }
}

// ---------------- fused MLP head — tensor core (mma.sync m16n8k16) ----------
__device__ __forceinline__ float leaky(float v) { return v > 0.f ? v : 0.01f * v; }

__device__ __forceinline__ void mma16816(float* d, unsigned a0, unsigned a1,
                                         unsigned a2, unsigned a3,
                                         unsigned b0, unsigned b1) {
    asm volatile(
        "mma.sync.aligned.m16n8k16.row.col.f32.f16.f16.f32 "
        "{%0,%1,%2,%3}, {%4,%5,%6,%7}, {%8,%9}, {%0,%1,%2,%3};"
        : "+f"(d[0]), "+f"(d[1]), "+f"(d[2]), "+f"(d[3])
        : "r"(a0), "r"(a1), "r"(a2), "r"(a3), "r"(b0), "r"(b1));
}
__device__ __forceinline__ unsigned lds32(const __half* p) {
    return *(const unsigned*)p;
}

// 64 nodes/block, 256 threads = 8 warps.
// smem arena: xh[64][136] fp16 (17408 B) | h1h[64][72] fp16 (9216 B)
// h2h[64][40] aliases xh; h3h[64][36] aliases h1h.
__global__ void __launch_bounds__(256) k_mlp(
    const float* __restrict__ feat,
    const float* __restrict__ b1, const float* __restrict__ b2,
    const float* __restrict__ b3, const float* __restrict__ W4,
    float* __restrict__ out, int Ntot)
{
    __shared__ __align__(16) char smarena[17408 + 9216];
    __half* xh  = (__half*)smarena;              // [64][136]
    __half* h1h = (__half*)(smarena + 17408);    // [64][72]
    __half* h2h = (__half*)smarena;              // [64][40]   (after GEMM2)
    __half* h3h = (__half*)(smarena + 17408);    // [64][36]   (after GEMM3)

    int t  = threadIdx.x;
    int nb = blockIdx.x * 64;

    // ---- stage x as fp16: xh[n][k] ----
    for (int i = t; i < 64 * 32; i += 256) {
        int n  = i >> 5;
        int c4 = i & 31;
        int gn = nb + n;
        uint2 o = make_uint2(0u, 0u);
        if (gn < Ntot) {
            int sm_ = g_srcmap[gn];
            if (sm_ > 0) {
                o = __ldg(((const uint2*)g_h1) + (size_t)(sm_ - 1) * 32 + c4);
            } else {
                float4 v = __ldg(((const float4*)feat) + (size_t)gn * 32 + c4);
                *(__half2*)&o.x = __floats2half2_rn(v.x, v.y);
                *(__half2*)&o.y = __floats2half2_rn(v.z, v.w);
            }
        }
        *(uint2*)&xh[n * 136 + c4 * 4] = o;
    }
    __syncthreads();

    int lane = t & 31, w = t >> 5;
    int r  = lane >> 2;          // fragment row / B col within n8
    int q2 = (lane & 3) * 2;     // fragment k-pair offset

    // ---- GEMM1 (mma): [64x128] @ W1t -> h1 [64x64] ----
    {
        int m0 = (w & 3) * 16, n0 = (w >> 2) * 32;
        float d[4][4];
#pragma unroll
        for (int i = 0; i < 4; i++) { d[i][0] = d[i][1] = d[i][2] = d[i][3] = 0.f; }
#pragma unroll
        for (int ks = 0; ks < 8; ks++) {
            int kb = ks * 16;
            const __half* ar = &xh[(m0 + r) * 136 + kb + q2];
            unsigned A0 = lds32(ar);
            unsigned A1 = lds32(ar + 8 * 136);
            unsigned A2 = lds32(ar + 8);
            unsigned A3 = lds32(ar + 8 * 136 + 8);
#pragma unroll
            for (int nt = 0; nt < 4; nt++) {
                const __half* br = &g_w1t[(n0 + nt * 8 + r) * 136 + kb + q2];
                unsigned B0 = lds32(br);
                unsigned B1 = lds32(br + 8);
                mma16816(d[nt], A0, A1, A2, A3, B0, B1);
            }
        }
        // epilogue: bias + leaky + fp16 -> h1h
#pragma unroll
        for (int nt = 0; nt < 4; nt++) {
            int c0 = n0 + nt * 8 + q2;
            float bb0 = __ldg(b1 + c0), bb1 = __ldg(b1 + c0 + 1);
            *(__half2*)&h1h[(m0 + r) * 72 + c0] =
                __floats2half2_rn(leaky(d[nt][0] + bb0), leaky(d[nt][1] + bb1));
            *(__half2*)&h1h[(m0 + r + 8) * 72 + c0] =
                __floats2half2_rn(leaky(d[nt][2] + bb0), leaky(d[nt][3] + bb1));
        }
    }
    __syncthreads();

    // ---- GEMM2 (mma): [64x64] @ W2t -> h2 [64x32] (h2h aliases xh) ----
    {
        int m0 = (w & 3) * 16, n0 = (w >> 2) * 16;
        float d[2][4];
#pragma unroll
        for (int i = 0; i < 2; i++) { d[i][0] = d[i][1] = d[i][2] = d[i][3] = 0.f; }
#pragma unroll
        for (int ks = 0; ks < 4; ks++) {
            int kb = ks * 16;
            const __half* ar = &h1h[(m0 + r) * 72 + kb + q2];
            unsigned A0 = lds32(ar);
            unsigned A1 = lds32(ar + 8 * 72);
            unsigned A2 = lds32(ar + 8);
            unsigned A3 = lds32(ar + 8 * 72 + 8);
#pragma unroll
            for (int nt = 0; nt < 2; nt++) {
                const __half* br = &g_w2t[(n0 + nt * 8 + r) * 72 + kb + q2];
                unsigned B0 = lds32(br);
                unsigned B1 = lds32(br + 8);
                mma16816(d[nt], A0, A1, A2, A3, B0, B1);
            }
        }
        __syncthreads();   // all h1h-as-input reads done... (see note below)
#pragma unroll
        for (int nt = 0; nt < 2; nt++) {
            int c0 = n0 + nt * 8 + q2;
            float bb0 = __ldg(b2 + c0), bb1 = __ldg(b2 + c0 + 1);
            *(__half2*)&h2h[(m0 + r) * 40 + c0] =
                __floats2half2_rn(leaky(d[nt][0] + bb0), leaky(d[nt][1] + bb1));
            *(__half2*)&h2h[(m0 + r + 8) * 40 + c0] =
                __floats2half2_rn(leaky(d[nt][2] + bb0), leaky(d[nt][3] + bb1));
        }
    }
    __syncthreads();

    // ---- GEMM3 (mma): [64x32] @ W3t -> h3 [64x24] (h3h aliases h1h) ----
    {
#pragma unroll
        for (int pass = 0; pass < 2; pass++) {
            int tid = w + pass * 8;
            if (tid >= 12) break;
            int m0 = (tid & 3) * 16, ntile = tid >> 2;
            int n0 = ntile * 8;
            float d[4] = {0.f, 0.f, 0.f, 0.f};
#pragma unroll
            for (int ks = 0; ks < 2; ks++) {
                int kb = ks * 16;
                const __half* ar = &h2h[(m0 + r) * 40 + kb + q2];
                unsigned A0 = lds32(ar);
                unsigned A1 = lds32(ar + 8 * 40);
                unsigned A2 = lds32(ar + 8);
                unsigned A3 = lds32(ar + 8 * 40 + 8);
                const __half* br = &g_w3t[(n0 + r) * 40 + kb + q2];
                unsigned B0 = lds32(br);
                unsigned B1 = lds32(br + 8);
                mma16816(d, A0, A1, A2, A3, B0, B1);
            }
            int c0 = n0 + q2;
            float bb0 = (c0 < 21) ? __ldg(b3 + c0) : 0.f;
            float bb1 = (c0 + 1 < 21) ? __ldg(b3 + c0 + 1) : 0.f;
            *(__half2*)&h3h[(m0 + r) * 36 + c0] =
                __floats2half2_rn(leaky(d[0] + bb0), leaky(d[1] + bb1));
            *(__half2*)&h3h[(m0 + r + 8) * 36 + c0] =
                __floats2half2_rn(leaky(d[2] + bb0), leaky(d[3] + bb1));
        }
    }
    __syncthreads();

    // ---- GEMM4 + sigmoid: [64x21] @ W4[21x1] ----
    if (t < 64) {
        int gn = nb + t;
        if (gn < Ntot) {
            float s = 0.f;
#pragma unroll
            for (int k = 0; k < 21; k++)
                s = fmaf(__half2float(h3h[t * 36 + k]), __ldg(W4 + k), s);
            out[gn] = 1.f / (1.f + expf(-s));
        }
    }
}

// ---------------- launch -----------------------------------------------------
extern "C" void kernel_launch(void* const* d_in, const int* in_sizes, int n_in,
                              void* d_out, int out_size) {
    const float* features = (const float*)d_in[0];
    const int*   index    = (const int*)d_in[1];
    const int*   erow     = (const int*)d_in[2];
    const int*   ecol     = (const int*)d_in[3];
    const float* eval_    = (const float*)d_in[4];
    const float* W1 = (const float*)d_in[5];
    const float* b1 = (const float*)d_in[6];
    const float* W2 = (const float*)d_in[7];
    const float* b2 = (const float*)d_in[8];
    const float* W3 = (const float*)d_in[9];
    const float* b3 = (const float*)d_in[10];
    const float* W4 = (const float*)d_in[11];

    int M = in_sizes[1];
    int E = in_sizes[2];
    int N = out_size;            // [N, 1] fp32 output
    float* out = (float*)d_out;

    const int TB = 256;
    int scanBlocks = (M + 1023) / 1024;   // 49 for M=50000 (g_bsum holds 64)

    k_init   <<<(M + TB - 1) / TB, TB>>>(M, W1, W2, W3);
    k_degcnt <<<(E + TB - 1) / TB, TB>>>(erow, eval_, E);
    k_scan1  <<<scanBlocks, 1024>>>(M);
    k_scan3  <<<(M + TB - 1) / TB, TB>>>(M, E, scanBlocks);
    k_scatter<<<(E + TB - 1) / TB, TB>>>(erow, ecol, eval_, E);
    k_gather0<<<(M * 32 + TB - 1) / TB, TB>>>(features, index, M);

    int spmmBlocks = (M + 15) / 16;       // 2 rows per warp, 8 warps per block
    k_spmm<<<spmmBlocks, TB>>>(0, M);     // h0 -> h1
    k_spmm<<<spmmBlocks, TB>>>(1, M);     // h1 -> h0
    k_spmm<<<spmmBlocks, TB>>>(0, M);     // h0 -> h1  (final in h1)

    k_mlp<<<(N + 63) / 64, 256>>>(features, b1, b2, b3, W4, out, N);
}